// round 16
// baseline (speedup 1.0000x reference)
#include <cuda_runtime.h>
#include <math.h>

// Problem constants
#define BATCH   8
#define SEQ     4096
#define M_TOTAL (BATCH * SEQ)   // 32768
#define NCODES  1024
#define KDIM    256
#define TOPM    3

// GEMM tiling
#define BM 128
#define BN 128
#define BK 16
#define NTILES (NCODES / BN)    // 8

// Per-(row, n-tile) max of sim: 32768 x 8 floats = 1 MB scratch
__device__ float g_rowmax[(size_t)M_TOTAL * NTILES];

// ---------------------------------------------------------------------------
// Packed fp32x2 helpers (sm_100 Blackwell dual-lane FP32, bit-exact vs fmaf)
// ---------------------------------------------------------------------------
__device__ __forceinline__ unsigned long long pack2(float x) {
    unsigned long long r;
    asm("mov.b64 %0, {%1, %1};" : "=l"(r) : "f"(x));
    return r;
}
__device__ __forceinline__ void fma2(unsigned long long& acc,
                                     unsigned long long a,
                                     unsigned long long b) {
    asm("fma.rn.f32x2 %0, %1, %2, %0;" : "+l"(acc) : "l"(a), "l"(b));
}
__device__ __forceinline__ float2 unpack2(unsigned long long v) {
    float2 f;
    asm("mov.b64 {%0, %1}, %2;" : "=f"(f.x), "=f"(f.y) : "l"(v));
    return f;
}

// ---------------------------------------------------------------------------
// Kernel 1: sim = q @ codes^T via fma.f32x2 (at the FFMA2 RF-banking roofline)
// BYTE-IDENTICAL to the R11..R15 GEMM (incl. tiny rowmax epilogue).
// Fusion attempts (R6, R12) both cost ~+90us via register pressure: keep out.
// ---------------------------------------------------------------------------
__global__ __launch_bounds__(256, 2)
void vq_sgemm_kernel(const float* __restrict__ A,    // [M_TOTAL, KDIM]
                     const float* __restrict__ Bm,   // [NCODES,  KDIM]
                     float* __restrict__ C)          // [M_TOTAL, NCODES]
{
    __shared__ float As[BK][BM + 4];   // stride 132 floats
    __shared__ float Bs[BK][BN + 4];

    const int bn0 = blockIdx.x * BN;
    const int bm0 = blockIdx.y * BM;
    const int tid = threadIdx.x;
    const int tx  = tid & 15;          // 0..15 -> N
    const int ty  = tid >> 4;          // 0..15 -> M

    const int lrow0 = tid >> 2;              // 0..63
    const int lrow1 = lrow0 + 64;            // 64..127
    const int lc4   = (tid & 3) * 4;         // 0,4,8,12

    const float* Aptr0 = &A[(size_t)(bm0 + lrow0) * KDIM + lc4];
    const float* Aptr1 = &A[(size_t)(bm0 + lrow1) * KDIM + lc4];
    const float* Bptr0 = &Bm[(size_t)(bn0 + lrow0) * KDIM + lc4];
    const float* Bptr1 = &Bm[(size_t)(bn0 + lrow1) * KDIM + lc4];

    unsigned long long acc2[8][4];
#pragma unroll
    for (int i = 0; i < 8; i++)
#pragma unroll
        for (int j = 0; j < 4; j++) acc2[i][j] = 0ull;

    // Prologue: load chunk 0
    float4 pa0 = *reinterpret_cast<const float4*>(Aptr0);
    float4 pa1 = *reinterpret_cast<const float4*>(Aptr1);
    float4 pb0 = *reinterpret_cast<const float4*>(Bptr0);
    float4 pb1 = *reinterpret_cast<const float4*>(Bptr1);

#pragma unroll 1
    for (int c = 0; c < KDIM / BK; c++) {
        As[lc4 + 0][lrow0] = pa0.x; As[lc4 + 1][lrow0] = pa0.y;
        As[lc4 + 2][lrow0] = pa0.z; As[lc4 + 3][lrow0] = pa0.w;
        As[lc4 + 0][lrow1] = pa1.x; As[lc4 + 1][lrow1] = pa1.y;
        As[lc4 + 2][lrow1] = pa1.z; As[lc4 + 3][lrow1] = pa1.w;
        Bs[lc4 + 0][lrow0] = pb0.x; Bs[lc4 + 1][lrow0] = pb0.y;
        Bs[lc4 + 2][lrow0] = pb0.z; Bs[lc4 + 3][lrow0] = pb0.w;
        Bs[lc4 + 0][lrow1] = pb1.x; Bs[lc4 + 1][lrow1] = pb1.y;
        Bs[lc4 + 2][lrow1] = pb1.z; Bs[lc4 + 3][lrow1] = pb1.w;
        __syncthreads();

        if (c + 1 < KDIM / BK) {
            int koff = (c + 1) * BK;
            pa0 = *reinterpret_cast<const float4*>(Aptr0 + koff);
            pa1 = *reinterpret_cast<const float4*>(Aptr1 + koff);
            pb0 = *reinterpret_cast<const float4*>(Bptr0 + koff);
            pb1 = *reinterpret_cast<const float4*>(Bptr1 + koff);
        }

#pragma unroll
        for (int kk = 0; kk < BK; kk++) {
            float4 a0 = *reinterpret_cast<const float4*>(&As[kk][ty * 4]);
            float4 a1 = *reinterpret_cast<const float4*>(&As[kk][64 + ty * 4]);
            ulonglong2 bp = *reinterpret_cast<const ulonglong2*>(&Bs[kk][tx * 4]);
            ulonglong2 bq = *reinterpret_cast<const ulonglong2*>(&Bs[kk][64 + tx * 4]);

            float av[8] = {a0.x, a0.y, a0.z, a0.w, a1.x, a1.y, a1.z, a1.w};
#pragma unroll
            for (int i = 0; i < 8; i++) {
                unsigned long long ap = pack2(av[i]);
                fma2(acc2[i][0], ap, bp.x);
                fma2(acc2[i][1], ap, bp.y);
                fma2(acc2[i][2], ap, bq.x);
                fma2(acc2[i][3], ap, bq.y);
            }
        }
        __syncthreads();
    }

#pragma unroll
    for (int ih = 0; ih < 2; ih++) {
#pragma unroll
        for (int ii = 0; ii < 4; ii++) {
            int i = ih * 4 + ii;
            int row = bm0 + ih * 64 + ty * 4 + ii;
            float* crow = &C[(size_t)row * NCODES + bn0];
            float2 c0 = unpack2(acc2[i][0]);
            float2 c1 = unpack2(acc2[i][1]);
            float2 c2 = unpack2(acc2[i][2]);
            float2 c3 = unpack2(acc2[i][3]);
            *reinterpret_cast<float4*>(&crow[tx * 4]) =
                make_float4(c0.x, c0.y, c1.x, c1.y);
            *reinterpret_cast<float4*>(&crow[64 + tx * 4]) =
                make_float4(c2.x, c2.y, c3.x, c3.y);

            // Row-tile max for the topk prefilter. Lanes [0..15] / [16..31]
            // hold two distinct rows; xor 1,2,4,8 stays within each group.
            float mrow = fmaxf(fmaxf(fmaxf(c0.x, c0.y), fmaxf(c1.x, c1.y)),
                               fmaxf(fmaxf(c2.x, c2.y), fmaxf(c3.x, c3.y)));
#pragma unroll
            for (int off = 1; off <= 8; off <<= 1)
                mrow = fmaxf(mrow, __shfl_xor_sync(0xffffffffu, mrow, off));
            if (tx == 0)
                g_rowmax[(size_t)row * NTILES + blockIdx.x] = mrow;
        }
    }
}

// ---------------------------------------------------------------------------
// Per-row scan body (exact-3 tiles, batched loads already in va/vb/vc).
// ---------------------------------------------------------------------------
__device__ __forceinline__ void topk_finish(
    int row, int lane,
    float4 va, float4 vb, float4 vc, int b0, int b1, int b2,
    float gg0, float gg1, float gg2,
    float* __restrict__ out_idx, float* __restrict__ out_w)
{
    const float NEG_INF = -__int_as_float(0x7f800000);
    float v0 = NEG_INF, v1 = NEG_INF, v2 = NEG_INF;
    int   i0 = 0x7fffffff, i1 = 0x7fffffff, i2 = 0x7fffffff;

    float vv[12] = {va.x, va.y, va.z, va.w,
                    vb.x, vb.y, vb.z, vb.w,
                    vc.x, vc.y, vc.z, vc.w};
    int   bb[3]  = {b0, b1, b2};
#pragma unroll
    for (int t = 0; t < 3; t++) {
#pragma unroll
        for (int e = 0; e < 4; e++) {
            float v = vv[t * 4 + e];
            int idx = bb[t] + e;
            if (v > v0)      { v2 = v1; i2 = i1; v1 = v0; i1 = i0; v0 = v; i0 = idx; }
            else if (v > v1) { v2 = v1; i2 = i1; v1 = v;  i1 = idx; }
            else if (v > v2) { v2 = v;  i2 = idx; }
        }
    }

    float lv[3] = {v0, v1, v2};
    int   li[3] = {i0, i1, i2};
    float tv[3];
    int   ti[3];
    int p = 0;
#pragma unroll
    for (int rr = 0; rr < 3; rr++) {
        float bv = (p < 3) ? lv[p] : NEG_INF;
        int   bi = (p < 3) ? li[p] : 0x7fffffff;
#pragma unroll
        for (int off = 16; off > 0; off >>= 1) {
            float ov = __shfl_xor_sync(0xffffffffu, bv, off);
            int   oi = __shfl_xor_sync(0xffffffffu, bi, off);
            if (ov > bv || (ov == bv && oi < bi)) { bv = ov; bi = oi; }
        }
        tv[rr] = bv; ti[rr] = bi;
        if (p < 3 && li[p] == bi) p++;
    }

    if (lane == 0) {
        float l0 = tv[0] + gg0;           // TAU = 1.0
        float l1 = tv[1] + gg1;
        float l2 = tv[2] + gg2;
        float mx = fmaxf(l0, fmaxf(l1, l2));
        float e0 = expf(l0 - mx);
        float e1 = expf(l1 - mx);
        float e2 = expf(l2 - mx);
        float inv = 1.0f / (e0 + e1 + e2);
        out_idx[row * 3 + 0] = (float)ti[0];
        out_idx[row * 3 + 1] = (float)ti[1];
        out_idx[row * 3 + 2] = (float)ti[2];
        out_w[row * 3 + 0] = e0 * inv;
        out_w[row * 3 + 1] = e1 * inv;
        out_w[row * 3 + 2] = e2 * inv;
    }
}

// ---------------------------------------------------------------------------
// Kernel 2: masked top-3 + Gumbel softmax; TWO rows per warp.
// R16 changes vs R15: each warp handles rows (r, r-1). mask/rowmax for both
// rows load together; both rows' 3 kept-tile loads batch (up to 6 LDG.128 in
// flight); row A's compute hides row B's load latency. Per-warp fixed costs
// amortize 2x; grid halves.
// ---------------------------------------------------------------------------
__global__ __launch_bounds__(128)
void vq_topk_kernel(const float* __restrict__ sim,   // [M_TOTAL, NCODES]
                    const int*   __restrict__ mask,  // [M_TOTAL]
                    const float* __restrict__ u,     // [M_TOTAL, 3]
                    float* __restrict__ out_idx,     // [M_TOTAL, 3] (as float)
                    float* __restrict__ out_w)       // [M_TOTAL, 3]
{
    const int wgl  = blockIdx.x * 4 + (threadIdx.x >> 5);
    const int rowA = (M_TOTAL - 1) - wgl * 2;         // reverse for L2 reuse
    const int rowB = rowA - 1;
    const int lane = threadIdx.x & 31;
    const int tl   = lane & 7;

    // Issue all four independent loads before any branch.
    const int   mA = mask[rowA];                      // warp-uniform
    const int   mB = mask[rowB];
    const float xA = g_rowmax[(size_t)rowA * NTILES + tl];
    const float xB = g_rowmax[(size_t)rowB * NTILES + tl];

    // Fixed outputs for masked rows (scan-independent).
    if (mA == 0 && lane == 0) {
#pragma unroll
        for (int rr = 0; rr < 3; rr++) {
            out_idx[rowA * 3 + rr] = (float)rr;
            out_w[rowA * 3 + rr]   = 0.0f;
        }
    }
    if (mB == 0 && lane == 0) {
#pragma unroll
        for (int rr = 0; rr < 3; rr++) {
            out_idx[rowB * 3 + rr] = (float)rr;
            out_w[rowB * 3 + rr]   = 0.0f;
        }
    }
    if (mA == 0 && mB == 0) return;                   // whole warp exits

    // --- Exact-3 tile selection per row: lexicographic rank
    // (value desc, tile asc) -> exactly 3 kept tiles each.
    int cntA = 0, cntB = 0;
#pragma unroll
    for (int j = 0; j < 8; j++) {
        float aj = __shfl_sync(0xffffffffu, xA, j);
        float bj = __shfl_sync(0xffffffffu, xB, j);
        cntA += ((aj > xA) || (aj == xA && j < tl)) ? 1 : 0;
        cntB += ((bj > xB) || (bj == xB && j < tl)) ? 1 : 0;
    }
    unsigned keepA = __ballot_sync(0xffffffffu, cntA <= 2) & 0xffu;
    unsigned keepB = __ballot_sync(0xffffffffu, cntB <= 2) & 0xffu;

    int a0 = __ffs(keepA) - 1;  keepA &= keepA - 1;
    int a1 = __ffs(keepA) - 1;  keepA &= keepA - 1;
    int a2 = __ffs(keepA) - 1;
    int c0 = __ffs(keepB) - 1;  keepB &= keepB - 1;
    int c1 = __ffs(keepB) - 1;  keepB &= keepB - 1;
    int c2 = __ffs(keepB) - 1;

    // --- Batched loads: up to 6 independent LDG.128 in flight ---
    const float* srA = sim + (size_t)rowA * NCODES;
    const float* srB = sim + (size_t)rowB * NCODES;
    int bA0 = a0 * 128 + lane * 4, bA1 = a1 * 128 + lane * 4, bA2 = a2 * 128 + lane * 4;
    int bB0 = c0 * 128 + lane * 4, bB1 = c1 * 128 + lane * 4, bB2 = c2 * 128 + lane * 4;
    float4 vA0, vA1, vA2, vB0, vB1, vB2;
    if (mA) {                                          // warp-uniform
        vA0 = *reinterpret_cast<const float4*>(&srA[bA0]);
        vA1 = *reinterpret_cast<const float4*>(&srA[bA1]);
        vA2 = *reinterpret_cast<const float4*>(&srA[bA2]);
    }
    if (mB) {
        vB0 = *reinterpret_cast<const float4*>(&srB[bB0]);
        vB1 = *reinterpret_cast<const float4*>(&srB[bB1]);
        vB2 = *reinterpret_cast<const float4*>(&srB[bB2]);
    }

    // --- Gumbel hoist for both rows (lane 0): MUFU latency hides under
    // the outstanding sim loads.
    float gA0 = 0.0f, gA1 = 0.0f, gA2 = 0.0f;
    float gB0 = 0.0f, gB1 = 0.0f, gB2 = 0.0f;
    if (lane == 0) {
        if (mA) {
            float u0 = fminf(fmaxf(u[rowA * 3 + 0], 1e-7f), 1.0f - 1e-7f);
            float u1 = fminf(fmaxf(u[rowA * 3 + 1], 1e-7f), 1.0f - 1e-7f);
            float u2 = fminf(fmaxf(u[rowA * 3 + 2], 1e-7f), 1.0f - 1e-7f);
            gA0 = -logf(fmaxf(-logf(u0), 1e-7f));
            gA1 = -logf(fmaxf(-logf(u1), 1e-7f));
            gA2 = -logf(fmaxf(-logf(u2), 1e-7f));
        }
        if (mB) {
            float u0 = fminf(fmaxf(u[rowB * 3 + 0], 1e-7f), 1.0f - 1e-7f);
            float u1 = fminf(fmaxf(u[rowB * 3 + 1], 1e-7f), 1.0f - 1e-7f);
            float u2 = fminf(fmaxf(u[rowB * 3 + 2], 1e-7f), 1.0f - 1e-7f);
            gB0 = -logf(fmaxf(-logf(u0), 1e-7f));
            gB1 = -logf(fmaxf(-logf(u1), 1e-7f));
            gB2 = -logf(fmaxf(-logf(u2), 1e-7f));
        }
    }

    // Row A compute overlaps row B's in-flight loads.
    if (mA)
        topk_finish(rowA, lane, vA0, vA1, vA2, bA0, bA1, bA2,
                    gA0, gA1, gA2, out_idx, out_w);
    if (mB)
        topk_finish(rowB, lane, vB0, vB1, vB2, bB0, bB1, bB2,
                    gB0, gB1, gB2, out_idx, out_w);
}

// ---------------------------------------------------------------------------
// Launch: d_out layout = [top_idx (B*N*3) | weights (B*N*3) | sim (B*N*K)]
// ---------------------------------------------------------------------------
extern "C" void kernel_launch(void* const* d_in, const int* in_sizes, int n_in,
                              void* d_out, int out_size)
{
    const float* q     = (const float*)d_in[0];   // [8,4096,256]
    const float* codes = (const float*)d_in[1];   // [1024,256]
    const int*   mask  = (const int*)  d_in[2];   // [8,4096]
    const float* u     = (const float*)d_in[3];   // [8,4096,3]

    float* out      = (float*)d_out;
    float* out_idx  = out;
    float* out_w    = out + (size_t)M_TOTAL * TOPM;
    float* sim      = out + (size_t)2 * M_TOTAL * TOPM;

    dim3 grid(NCODES / BN, M_TOTAL / BM);
    vq_sgemm_kernel<<<grid, 256>>>(q, codes, sim);

    vq_topk_kernel<<<M_TOTAL / 8, 128>>>(sim, mask, u, out_idx, out_w);
}